// round 8
// baseline (speedup 1.0000x reference)
#include <cuda_runtime.h>
#include <math.h>

#define L_LAYERS 2
#define NNEI 120
#define ED 64
#define HD 128
#define FDIM 384          // 3*HD
#define NW 32
#define NTHREADS 1024
#define SCALING 0.08838834764831845f   // HD^-0.5
#define LN_EPS 1e-5f

// shared memory layout (floats)
#define OFF_SX   0                         // 120*64   = 7680
#define OFF_SQ   7680                      // 120*128  = 15360 (q, later o)
#define OFF_SK   23040                     // 120*128  = 15360 (k swizzled; later aw2)
#define OFF_SV   38400                     // 120*128  = 15360
#define OFF_BUF  53760                     // 3840: weight staging
#define OFF_R    57600                     // 120*3
#define OFF_MASK 57960                     // 120
#define SMEM_FLOATS 58080                  // 232320 B <= 232448 limit

typedef unsigned long long u64;

__device__ __forceinline__ u64 ffma2(u64 a, u64 b, u64 c) {
    u64 d; asm("fma.rn.f32x2 %0, %1, %2, %3;" : "=l"(d) : "l"(a), "l"(b), "l"(c));
    return d;
}
__device__ __forceinline__ u64 pack2(float lo, float hi) {
    u64 d; asm("mov.b64 %0, {%1, %2};" : "=l"(d) : "f"(lo), "f"(hi));
    return d;
}
__device__ __forceinline__ float hsum2(u64 v) {
    float lo, hi; asm("mov.b64 {%0, %1}, %2;" : "=f"(lo), "=f"(hi) : "l"(v));
    return lo + hi;
}

__device__ __forceinline__ float warp_sum(float v) {
    #pragma unroll
    for (int o = 16; o; o >>= 1) v += __shfl_xor_sync(0xffffffffu, v, o);
    return v;
}
__device__ __forceinline__ float warp_max(float v) {
    #pragma unroll
    for (int o = 16; o; o >>= 1) v = fmaxf(v, __shfl_xor_sync(0xffffffffu, v, o));
    return v;
}

__global__ __launch_bounds__(NTHREADS, 1)
void nwa_kernel(const float* __restrict__ G,
                const int* __restrict__ maskp,          // bool arrives as int32
                const float* __restrict__ rp,
                const float* __restrict__ in_w, const float* __restrict__ in_b,
                const float* __restrict__ out_w, const float* __restrict__ out_b,
                const float* __restrict__ ln_g, const float* __restrict__ ln_b,
                float* __restrict__ out)
{
    extern __shared__ float sm[];
    float* sx    = sm + OFF_SX;
    float* sq    = sm + OFF_SQ;
    float* sk    = sm + OFF_SK;
    float* sv    = sm + OFF_SV;
    float* sbuf  = sm + OFF_BUF;
    float* sr    = sm + OFF_R;
    float* smask = sm + OFF_MASK;
    float4* sx4  = (float4*)sx;

    const int b = blockIdx.x;
    const int tid = threadIdx.x;
    const int w = tid >> 5;
    const int lane = tid & 31;

    // ---- load per-batch inputs ----
    {
        const float4* Gx = (const float4*)(G + (size_t)b * NNEI * ED);
        for (int i = tid; i < NNEI * ED / 4; i += NTHREADS) sx4[i] = Gx[i];
        const float* rb = rp + (size_t)b * NNEI * 3;
        for (int i = tid; i < NNEI * 3; i += NTHREADS) sr[i] = rb[i];
        if (tid < NNEI) smask[tid] = maskp[(size_t)b * NNEI + tid] ? 1.0f : 0.0f;
    }
    __syncthreads();

    for (int l = 0; l < L_LAYERS; l++) {
        // ========== Phase A: qkv = x @ in_w + in_b  (15 warps x 8 rows) ==========
        const float* Wl = in_w + (size_t)l * ED * FDIM;
        for (int fc = 0; fc < FDIM / 32; fc++) {
            // stage weight chunk pair-interleaved: sbuf[(e>>1)*64 + 2*j + (e&1)]
            for (int idx = tid; idx < ED * 32; idx += NTHREADS) {
                int e = idx >> 5, j = idx & 31;
                sbuf[(e >> 1) * 64 + 2 * j + (e & 1)] = Wl[e * FDIM + fc * 32 + j];
            }
            __syncthreads();
            if (w < 15) {
                u64 acc[8];
                #pragma unroll
                for (int i = 0; i < 8; i++) acc[i] = 0ull;
                #pragma unroll 2
                for (int k4 = 0; k4 < 16; k4++) {          // e = 4*k4 .. 4*k4+3
                    u64 wa = *(const u64*)(sbuf + (2 * k4) * 64 + 2 * lane);
                    u64 wb = *(const u64*)(sbuf + (2 * k4 + 1) * 64 + 2 * lane);
                    #pragma unroll
                    for (int i = 0; i < 8; i++) {
                        ulonglong2 xq = *(const ulonglong2*)(sx + (8 * w + i) * ED + 4 * k4);
                        acc[i] = ffma2(xq.x, wa, acc[i]);
                        acc[i] = ffma2(xq.y, wb, acc[i]);
                    }
                }
                int f = fc * 32 + lane;
                float bv = in_b[l * FDIM + f];
                #pragma unroll
                for (int i = 0; i < 8; i++) {
                    int n = 8 * w + i;
                    float v = hsum2(acc[i]) + bv;
                    if (f < HD)            sq[n * HD + f] = v;
                    else if (f < 2 * HD) { int hk = f - HD;
                                           sk[n * HD + (hk ^ ((4 * n) & 127))] = v; }
                    else                   sv[n * HD + (f - 2 * HD)] = v;
                }
            }
            __syncthreads();
        }

        // ========== Phase B: l2norm rows of q, k, v (k swizzle is a permutation) ==========
        for (int task = w; task < 3 * NNEI; task += NW) {
            int type = task / NNEI;   // 0=q, 1=k, 2=v
            int n = task - type * NNEI;
            float* base = (type == 0 ? sq : (type == 1 ? sk : sv)) + n * HD;
            float4 vv = ((float4*)base)[lane];
            float s = vv.x * vv.x + vv.y * vv.y + vv.z * vv.z + vv.w * vv.w;
            s = warp_sum(s);
            float sc = 1.0f / fmaxf(sqrtf(s), 1e-12f);
            if (type == 0) sc *= SCALING;
            vv.x *= sc; vv.y *= sc; vv.z *= sc; vv.w *= sc;
            ((float4*)base)[lane] = vv;
        }
        __syncthreads();

        // ========== QK^T: 30 warps x 4 rows ==========
        u64 acc[4][4];
        if (w < 30) {
            const int n0 = 4 * w;
            const int rot = 4 * lane;   // (4*m)&127 == 4*(m&31) == 4*lane, j-indep
            int offs[4];
            #pragma unroll
            for (int j = 0; j < 4; j++) {
                int m = lane + 32 * j;
                offs[j] = ((m < NNEI) ? m : 0) * HD;
            }
            #pragma unroll
            for (int r = 0; r < 4; r++)
                #pragma unroll
                for (int j = 0; j < 4; j++) acc[r][j] = 0ull;
            #pragma unroll 1
            for (int h = 0; h < HD; h += 4) {
                ulonglong2 q0 = *(const ulonglong2*)(sq + (n0 + 0) * HD + h);
                ulonglong2 q1 = *(const ulonglong2*)(sq + (n0 + 1) * HD + h);
                ulonglong2 q2 = *(const ulonglong2*)(sq + (n0 + 2) * HD + h);
                ulonglong2 q3 = *(const ulonglong2*)(sq + (n0 + 3) * HD + h);
                #pragma unroll
                for (int j = 0; j < 4; j++) {
                    ulonglong2 kk = *(const ulonglong2*)(sk + offs[j] + (h ^ rot));
                    acc[0][j] = ffma2(q0.x, kk.x, acc[0][j]);
                    acc[0][j] = ffma2(q0.y, kk.y, acc[0][j]);
                    acc[1][j] = ffma2(q1.x, kk.x, acc[1][j]);
                    acc[1][j] = ffma2(q1.y, kk.y, acc[1][j]);
                    acc[2][j] = ffma2(q2.x, kk.x, acc[2][j]);
                    acc[2][j] = ffma2(q2.y, kk.y, acc[2][j]);
                    acc[3][j] = ffma2(q3.x, kk.x, acc[3][j]);
                    acc[3][j] = ffma2(q3.y, kk.y, acc[3][j]);
                }
            }
        }
        __syncthreads();   // all reads of sk complete; sk becomes aw2

        // ========== softmax + mask + angle; store aw into aw2 (= sk region) ==========
        float* aw2 = sk;   // aw2[m*128 + ((n + 4m)&127)] = aw(n, m)
        if (w < 30) {
            const int n0 = 4 * w;
            float smk[4], rmx[4], rmy[4], rmz[4];
            #pragma unroll
            for (int j = 0; j < 4; j++) {
                int m = lane + 32 * j;
                int mc = (m < NNEI) ? m : 0;
                smk[j] = (m < NNEI) ? smask[m] : 0.0f;
                rmx[j] = sr[mc * 3]; rmy[j] = sr[mc * 3 + 1]; rmz[j] = sr[mc * 3 + 2];
            }
            float awr[4][4];
            #pragma unroll
            for (int r = 0; r < 4; r++) {
                int n = n0 + r;
                float lg[4]; float mx = -1e30f;
                #pragma unroll
                for (int j = 0; j < 4; j++) {
                    float s = hsum2(acc[r][j]);
                    lg[j] = (smk[j] > 0.5f) ? s : -1e30f;
                    mx = fmaxf(mx, lg[j]);
                }
                mx = warp_max(mx);
                float ex[4], ssum = 0.f;
                #pragma unroll
                for (int j = 0; j < 4; j++) { ex[j] = __expf(lg[j] - mx); ssum += ex[j]; }
                ssum = warp_sum(ssum);
                float coef = smask[n] / ssum;
                float rn0 = sr[n * 3], rn1 = sr[n * 3 + 1], rn2 = sr[n * 3 + 2];
                #pragma unroll
                for (int j = 0; j < 4; j++) {
                    float ang = rn0 * rmx[j] + rn1 * rmy[j] + rn2 * rmz[j];
                    awr[r][j] = ex[j] * coef * ang;   // 0 for masked/invalid m
                }
            }
            #pragma unroll
            for (int j = 0; j < 4; j++) {
                int m = lane + 32 * j;
                if (m < NNEI) {
                    int col = (n0 + 4 * m) & 127;
                    float4 v4 = make_float4(awr[0][j], awr[1][j], awr[2][j], awr[3][j]);
                    *(float4*)(aw2 + m * 128 + col) = v4;
                }
            }
        }
        __syncthreads();

        // ========== AV: 15 warps x 8 rows, v shared, aw broadcast ==========
        if (w < 15) {
            const int nb = 8 * w;
            u64 oa[8], ob[8];
            #pragma unroll
            for (int r = 0; r < 8; r++) { oa[r] = 0ull; ob[r] = 0ull; }
            #pragma unroll 2
            for (int m = 0; m < NNEI; m++) {
                int col = (nb + 4 * m) & 127;
                float4 alo = *(const float4*)(aw2 + m * 128 + col);
                float4 ahi = *(const float4*)(aw2 + m * 128 + ((col + 4) & 127));
                ulonglong2 vv = *(const ulonglong2*)(sv + m * HD + 4 * lane);
                u64 p;
                p = pack2(alo.x, alo.x); oa[0] = ffma2(p, vv.x, oa[0]); ob[0] = ffma2(p, vv.y, ob[0]);
                p = pack2(alo.y, alo.y); oa[1] = ffma2(p, vv.x, oa[1]); ob[1] = ffma2(p, vv.y, ob[1]);
                p = pack2(alo.z, alo.z); oa[2] = ffma2(p, vv.x, oa[2]); ob[2] = ffma2(p, vv.y, ob[2]);
                p = pack2(alo.w, alo.w); oa[3] = ffma2(p, vv.x, oa[3]); ob[3] = ffma2(p, vv.y, ob[3]);
                p = pack2(ahi.x, ahi.x); oa[4] = ffma2(p, vv.x, oa[4]); ob[4] = ffma2(p, vv.y, ob[4]);
                p = pack2(ahi.y, ahi.y); oa[5] = ffma2(p, vv.x, oa[5]); ob[5] = ffma2(p, vv.y, ob[5]);
                p = pack2(ahi.z, ahi.z); oa[6] = ffma2(p, vv.x, oa[6]); ob[6] = ffma2(p, vv.y, ob[6]);
                p = pack2(ahi.w, ahi.w); oa[7] = ffma2(p, vv.x, oa[7]); ob[7] = ffma2(p, vv.y, ob[7]);
            }
            #pragma unroll
            for (int r = 0; r < 8; r++) {
                ulonglong2 ov; ov.x = oa[r]; ov.y = ob[r];
                *(ulonglong2*)(sq + (nb + r) * HD + 4 * lane) = ov;  // q <- o
            }
        }
        __syncthreads();

        // ========== Phase F: x = LN(residual + o @ out_w + out_b)  (packed over h) ==========
        const float* Ow = out_w + (size_t)l * HD * ED;
        u64 accF[4][2];
        #pragma unroll
        for (int i = 0; i < 4; i++) { accF[i][0] = 0ull; accF[i][1] = 0ull; }
        for (int hc = 0; hc < 4; hc++) {
            // stage 32 h x 64 e chunk, pair-interleaved over h
            for (int idx = tid; idx < 32 * ED; idx += NTHREADS) {
                int hl = idx >> 6, e = idx & 63;
                sbuf[(hl >> 1) * 128 + 2 * e + (hl & 1)] = Ow[(hc * 32 + hl) * ED + e];
            }
            __syncthreads();
            #pragma unroll 4
            for (int h2 = 0; h2 < 16; h2++) {
                u64 w0 = *(const u64*)(sbuf + h2 * 128 + 2 * lane);
                u64 w1 = *(const u64*)(sbuf + h2 * 128 + 64 + 2 * lane);
                #pragma unroll
                for (int i = 0; i < 4; i++) {
                    int n = w + 32 * i;
                    if (n < NNEI) {
                        u64 op = *(const u64*)(sq + n * HD + hc * 32 + 2 * h2);
                        accF[i][0] = ffma2(op, w0, accF[i][0]);
                        accF[i][1] = ffma2(op, w1, accF[i][1]);
                    }
                }
            }
            __syncthreads();
        }
        {
            float ob0 = out_b[l * ED + lane],      ob1 = out_b[l * ED + 32 + lane];
            float g0  = ln_g[l * ED + lane],       g1  = ln_g[l * ED + 32 + lane];
            float bb0 = ln_b[l * ED + lane],       bb1 = ln_b[l * ED + 32 + lane];
            #pragma unroll
            for (int i = 0; i < 4; i++) {
                int n = w + 32 * i;
                if (n < NNEI) {
                    float x0 = sx[n * ED + lane]      + hsum2(accF[i][0]) + ob0;
                    float x1 = sx[n * ED + 32 + lane] + hsum2(accF[i][1]) + ob1;
                    float mu = warp_sum(x0 + x1) * (1.0f / 64.0f);
                    float d0 = x0 - mu, d1 = x1 - mu;
                    float var = warp_sum(d0 * d0 + d1 * d1) * (1.0f / 64.0f);
                    float rs = rsqrtf(var + LN_EPS);
                    sx[n * ED + lane]      = d0 * rs * g0 + bb0;
                    sx[n * ED + 32 + lane] = d1 * rs * g1 + bb1;
                }
            }
        }
        __syncthreads();
    }

    // ---- write output ----
    float4* outp = (float4*)(out + (size_t)b * NNEI * ED);
    for (int i = tid; i < NNEI * ED / 4; i += NTHREADS) outp[i] = sx4[i];
}

extern "C" void kernel_launch(void* const* d_in, const int* in_sizes, int n_in,
                              void* d_out, int out_size) {
    const float* G     = (const float*)d_in[0];
    const int* mk      = (const int*)d_in[1];      // bool -> int32 per harness dtypes
    const float* r     = (const float*)d_in[2];
    const float* in_w  = (const float*)d_in[3];
    const float* in_b  = (const float*)d_in[4];
    const float* out_w = (const float*)d_in[5];
    const float* out_b = (const float*)d_in[6];
    const float* ln_g  = (const float*)d_in[7];
    const float* ln_b  = (const float*)d_in[8];
    float* out         = (float*)d_out;

    int B = in_sizes[0] / (NNEI * ED);

    cudaFuncSetAttribute(nwa_kernel, cudaFuncAttributeMaxDynamicSharedMemorySize,
                         SMEM_FLOATS * sizeof(float));
    nwa_kernel<<<B, NTHREADS, SMEM_FLOATS * sizeof(float)>>>(
        G, mk, r, in_w, in_b, out_w, out_b, ln_g, ln_b, out);
}

// round 10
// speedup vs baseline: 1.4153x; 1.4153x over previous
#include <cuda_runtime.h>
#include <math.h>

#define L_LAYERS 2
#define NNEI 120
#define ED 64
#define HD 128
#define FDIM 384          // 3*HD
#define NW 32
#define NTHREADS 1024
#define SCALING 0.08838834764831845f   // HD^-0.5
#define LN_EPS 1e-5f

// shared memory layout (floats)
#define OFF_SX   0                         // 120*64   = 7680
#define OFF_SQ   7680                      // 120*128  = 15360 (q, later o)
#define OFF_SK   23040                     // 120*128  = 15360 (k swizzled; later aw2)
#define OFF_SV   38400                     // 120*128  = 15360
#define OFF_BUF  53760                     // 3840: weight staging
#define OFF_R    57600                     // 120*3
#define OFF_MASK 57960                     // 120
#define SMEM_FLOATS 58080                  // 232320 B <= 232448 limit

typedef unsigned long long u64;

__device__ __forceinline__ u64 ffma2(u64 a, u64 b, u64 c) {
    u64 d; asm("fma.rn.f32x2 %0, %1, %2, %3;" : "=l"(d) : "l"(a), "l"(b), "l"(c));
    return d;
}
__device__ __forceinline__ u64 pack2(float lo, float hi) {
    u64 d; asm("mov.b64 %0, {%1, %2};" : "=l"(d) : "f"(lo), "f"(hi));
    return d;
}
__device__ __forceinline__ float hsum2(u64 v) {
    float lo, hi; asm("mov.b64 {%0, %1}, %2;" : "=f"(lo), "=f"(hi) : "l"(v));
    return lo + hi;
}

__device__ __forceinline__ float warp_sum(float v) {
    #pragma unroll
    for (int o = 16; o; o >>= 1) v += __shfl_xor_sync(0xffffffffu, v, o);
    return v;
}
__device__ __forceinline__ float warp_max(float v) {
    #pragma unroll
    for (int o = 16; o; o >>= 1) v = fmaxf(v, __shfl_xor_sync(0xffffffffu, v, o));
    return v;
}

__global__ __launch_bounds__(NTHREADS, 1)
void nwa_kernel(const float* __restrict__ G,
                const int* __restrict__ maskp,          // bool arrives as int32
                const float* __restrict__ rp,
                const float* __restrict__ in_w, const float* __restrict__ in_b,
                const float* __restrict__ out_w, const float* __restrict__ out_b,
                const float* __restrict__ ln_g, const float* __restrict__ ln_b,
                float* __restrict__ out)
{
    extern __shared__ float sm[];
    float* sx    = sm + OFF_SX;
    float* sq    = sm + OFF_SQ;
    float* sk    = sm + OFF_SK;
    float* sv    = sm + OFF_SV;
    float* sbuf  = sm + OFF_BUF;
    float* sr    = sm + OFF_R;
    float* smask = sm + OFF_MASK;
    float4* sx4  = (float4*)sx;

    const int b = blockIdx.x;
    const int tid = threadIdx.x;
    const int w = tid >> 5;
    const int lane = tid & 31;

    // ---- load per-batch inputs ----
    {
        const float4* Gx = (const float4*)(G + (size_t)b * NNEI * ED);
        for (int i = tid; i < NNEI * ED / 4; i += NTHREADS) sx4[i] = Gx[i];
        const float* rb = rp + (size_t)b * NNEI * 3;
        for (int i = tid; i < NNEI * 3; i += NTHREADS) sr[i] = rb[i];
        if (tid < NNEI) smask[tid] = maskp[(size_t)b * NNEI + tid] ? 1.0f : 0.0f;
    }
    __syncthreads();

    for (int l = 0; l < L_LAYERS; l++) {
        // ========== Phase A: qkv = x @ in_w + in_b  (20 warps x 6 rows) ==========
        const float* Wl = in_w + (size_t)l * ED * FDIM;
        for (int fc = 0; fc < FDIM / 32; fc++) {
            // stage weight chunk pair-interleaved: sbuf[(e>>1)*64 + 2*j + (e&1)]
            for (int idx = tid; idx < ED * 32; idx += NTHREADS) {
                int e = idx >> 5, j = idx & 31;
                sbuf[(e >> 1) * 64 + 2 * j + (e & 1)] = Wl[e * FDIM + fc * 32 + j];
            }
            __syncthreads();
            if (w < 20) {
                u64 acc[6];
                #pragma unroll
                for (int i = 0; i < 6; i++) acc[i] = 0ull;
                #pragma unroll 2
                for (int k4 = 0; k4 < 16; k4++) {          // e = 4*k4 .. 4*k4+3
                    u64 wa = *(const u64*)(sbuf + (2 * k4) * 64 + 2 * lane);
                    u64 wb = *(const u64*)(sbuf + (2 * k4 + 1) * 64 + 2 * lane);
                    #pragma unroll
                    for (int i = 0; i < 6; i++) {
                        ulonglong2 xq = *(const ulonglong2*)(sx + (6 * w + i) * ED + 4 * k4);
                        acc[i] = ffma2(xq.x, wa, acc[i]);
                        acc[i] = ffma2(xq.y, wb, acc[i]);
                    }
                }
                int f = fc * 32 + lane;
                float bv = in_b[l * FDIM + f];
                #pragma unroll
                for (int i = 0; i < 6; i++) {
                    int n = 6 * w + i;
                    float v = hsum2(acc[i]) + bv;
                    if (f < HD)            sq[n * HD + f] = v;
                    else if (f < 2 * HD) { int hk = f - HD;
                                           sk[n * HD + (hk ^ ((4 * n) & 127))] = v; }
                    else                   sv[n * HD + (f - 2 * HD)] = v;
                }
            }
            __syncthreads();
        }

        // ========== Phase B: l2norm rows of q, k, v (k swizzle is a permutation) ==========
        for (int task = w; task < 3 * NNEI; task += NW) {
            int type = task / NNEI;   // 0=q, 1=k, 2=v
            int n = task - type * NNEI;
            float* base = (type == 0 ? sq : (type == 1 ? sk : sv)) + n * HD;
            float4 vv = ((float4*)base)[lane];
            float s = vv.x * vv.x + vv.y * vv.y + vv.z * vv.z + vv.w * vv.w;
            s = warp_sum(s);
            float sc = 1.0f / fmaxf(sqrtf(s), 1e-12f);
            if (type == 0) sc *= SCALING;
            vv.x *= sc; vv.y *= sc; vv.z *= sc; vv.w *= sc;
            ((float4*)base)[lane] = vv;
        }
        __syncthreads();

        // ========== QK^T: 30 warps x 4 rows ==========
        u64 acc[4][4];
        if (w < 30) {
            const int n0 = 4 * w;
            const int rot = 4 * lane;   // (4*m)&127 == 4*(m&31) == 4*lane, j-indep
            int offs[4];
            #pragma unroll
            for (int j = 0; j < 4; j++) {
                int m = lane + 32 * j;
                offs[j] = ((m < NNEI) ? m : 0) * HD;
            }
            #pragma unroll
            for (int r = 0; r < 4; r++)
                #pragma unroll
                for (int j = 0; j < 4; j++) acc[r][j] = 0ull;
            #pragma unroll 1
            for (int h = 0; h < HD; h += 4) {
                ulonglong2 q0 = *(const ulonglong2*)(sq + (n0 + 0) * HD + h);
                ulonglong2 q1 = *(const ulonglong2*)(sq + (n0 + 1) * HD + h);
                ulonglong2 q2 = *(const ulonglong2*)(sq + (n0 + 2) * HD + h);
                ulonglong2 q3 = *(const ulonglong2*)(sq + (n0 + 3) * HD + h);
                #pragma unroll
                for (int j = 0; j < 4; j++) {
                    ulonglong2 kk = *(const ulonglong2*)(sk + offs[j] + (h ^ rot));
                    acc[0][j] = ffma2(q0.x, kk.x, acc[0][j]);
                    acc[0][j] = ffma2(q0.y, kk.y, acc[0][j]);
                    acc[1][j] = ffma2(q1.x, kk.x, acc[1][j]);
                    acc[1][j] = ffma2(q1.y, kk.y, acc[1][j]);
                    acc[2][j] = ffma2(q2.x, kk.x, acc[2][j]);
                    acc[2][j] = ffma2(q2.y, kk.y, acc[2][j]);
                    acc[3][j] = ffma2(q3.x, kk.x, acc[3][j]);
                    acc[3][j] = ffma2(q3.y, kk.y, acc[3][j]);
                }
            }
        }
        __syncthreads();   // all reads of sk complete; sk becomes aw2

        // ========== softmax + mask + angle; store aw into aw2 (= sk region) ==========
        float* aw2 = sk;   // aw2[m*128 + ((n + 4m)&127)] = aw(n, m)
        if (w < 30) {
            const int n0 = 4 * w;
            float smk[4], rmx[4], rmy[4], rmz[4];
            #pragma unroll
            for (int j = 0; j < 4; j++) {
                int m = lane + 32 * j;
                int mc = (m < NNEI) ? m : 0;
                smk[j] = (m < NNEI) ? smask[m] : 0.0f;
                rmx[j] = sr[mc * 3]; rmy[j] = sr[mc * 3 + 1]; rmz[j] = sr[mc * 3 + 2];
            }
            float awr[4][4];
            #pragma unroll
            for (int r = 0; r < 4; r++) {
                int n = n0 + r;
                float lg[4]; float mx = -1e30f;
                #pragma unroll
                for (int j = 0; j < 4; j++) {
                    float s = hsum2(acc[r][j]);
                    lg[j] = (smk[j] > 0.5f) ? s : -1e30f;
                    mx = fmaxf(mx, lg[j]);
                }
                mx = warp_max(mx);
                float ex[4], ssum = 0.f;
                #pragma unroll
                for (int j = 0; j < 4; j++) { ex[j] = __expf(lg[j] - mx); ssum += ex[j]; }
                ssum = warp_sum(ssum);
                float coef = smask[n] / ssum;
                float rn0 = sr[n * 3], rn1 = sr[n * 3 + 1], rn2 = sr[n * 3 + 2];
                #pragma unroll
                for (int j = 0; j < 4; j++) {
                    float ang = rn0 * rmx[j] + rn1 * rmy[j] + rn2 * rmz[j];
                    awr[r][j] = ex[j] * coef * ang;   // 0 for masked/invalid m
                }
            }
            #pragma unroll
            for (int j = 0; j < 4; j++) {
                int m = lane + 32 * j;
                if (m < NNEI) {
                    int col = (n0 + 4 * m) & 127;
                    float4 v4 = make_float4(awr[0][j], awr[1][j], awr[2][j], awr[3][j]);
                    *(float4*)(aw2 + m * 128 + col) = v4;
                }
            }
        }
        __syncthreads();

        // ========== AV: 30 warps x 4 rows, v shared, aw float4 broadcast ==========
        if (w < 30) {
            const int nb = 4 * w;
            u64 oa[4], ob[4];
            #pragma unroll
            for (int r = 0; r < 4; r++) { oa[r] = 0ull; ob[r] = 0ull; }
            #pragma unroll 2
            for (int m = 0; m < NNEI; m++) {
                int col = (nb + 4 * m) & 127;
                float4 alo = *(const float4*)(aw2 + m * 128 + col);
                ulonglong2 vv = *(const ulonglong2*)(sv + m * HD + 4 * lane);
                u64 p;
                p = pack2(alo.x, alo.x); oa[0] = ffma2(p, vv.x, oa[0]); ob[0] = ffma2(p, vv.y, ob[0]);
                p = pack2(alo.y, alo.y); oa[1] = ffma2(p, vv.x, oa[1]); ob[1] = ffma2(p, vv.y, ob[1]);
                p = pack2(alo.z, alo.z); oa[2] = ffma2(p, vv.x, oa[2]); ob[2] = ffma2(p, vv.y, ob[2]);
                p = pack2(alo.w, alo.w); oa[3] = ffma2(p, vv.x, oa[3]); ob[3] = ffma2(p, vv.y, ob[3]);
            }
            #pragma unroll
            for (int r = 0; r < 4; r++) {
                ulonglong2 ov; ov.x = oa[r]; ov.y = ob[r];
                *(ulonglong2*)(sq + (nb + r) * HD + 4 * lane) = ov;  // q <- o
            }
        }
        __syncthreads();

        // ========== Phase F: x = LN(residual + o @ out_w + out_b)  (packed over h) ==========
        const float* Ow = out_w + (size_t)l * HD * ED;
        u64 accF[4][2];
        #pragma unroll
        for (int i = 0; i < 4; i++) { accF[i][0] = 0ull; accF[i][1] = 0ull; }
        for (int hc = 0; hc < 4; hc++) {
            // stage 32 h x 64 e chunk, pair-interleaved over h
            for (int idx = tid; idx < 32 * ED; idx += NTHREADS) {
                int hl = idx >> 6, e = idx & 63;
                sbuf[(hl >> 1) * 128 + 2 * e + (hl & 1)] = Ow[(hc * 32 + hl) * ED + e];
            }
            __syncthreads();
            #pragma unroll 4
            for (int h2 = 0; h2 < 16; h2++) {
                u64 w0 = *(const u64*)(sbuf + h2 * 128 + 2 * lane);
                u64 w1 = *(const u64*)(sbuf + h2 * 128 + 64 + 2 * lane);
                #pragma unroll
                for (int i = 0; i < 4; i++) {
                    int n = w + 32 * i;
                    if (n < NNEI) {
                        u64 op = *(const u64*)(sq + n * HD + hc * 32 + 2 * h2);
                        accF[i][0] = ffma2(op, w0, accF[i][0]);
                        accF[i][1] = ffma2(op, w1, accF[i][1]);
                    }
                }
            }
            __syncthreads();
        }
        {
            float ob0 = out_b[l * ED + lane],      ob1 = out_b[l * ED + 32 + lane];
            float g0  = ln_g[l * ED + lane],       g1  = ln_g[l * ED + 32 + lane];
            float bb0 = ln_b[l * ED + lane],       bb1 = ln_b[l * ED + 32 + lane];
            #pragma unroll
            for (int i = 0; i < 4; i++) {
                int n = w + 32 * i;
                if (n < NNEI) {
                    float x0 = sx[n * ED + lane]      + hsum2(accF[i][0]) + ob0;
                    float x1 = sx[n * ED + 32 + lane] + hsum2(accF[i][1]) + ob1;
                    float mu = warp_sum(x0 + x1) * (1.0f / 64.0f);
                    float d0 = x0 - mu, d1 = x1 - mu;
                    float var = warp_sum(d0 * d0 + d1 * d1) * (1.0f / 64.0f);
                    float rs = rsqrtf(var + LN_EPS);
                    sx[n * ED + lane]      = d0 * rs * g0 + bb0;
                    sx[n * ED + 32 + lane] = d1 * rs * g1 + bb1;
                }
            }
        }
        __syncthreads();
    }

    // ---- write output ----
    float4* outp = (float4*)(out + (size_t)b * NNEI * ED);
    for (int i = tid; i < NNEI * ED / 4; i += NTHREADS) outp[i] = sx4[i];
}

extern "C" void kernel_launch(void* const* d_in, const int* in_sizes, int n_in,
                              void* d_out, int out_size) {
    const float* G     = (const float*)d_in[0];
    const int* mk      = (const int*)d_in[1];      // bool -> int32 per harness dtypes
    const float* r     = (const float*)d_in[2];
    const float* in_w  = (const float*)d_in[3];
    const float* in_b  = (const float*)d_in[4];
    const float* out_w = (const float*)d_in[5];
    const float* out_b = (const float*)d_in[6];
    const float* ln_g  = (const float*)d_in[7];
    const float* ln_b  = (const float*)d_in[8];
    float* out         = (float*)d_out;

    int B = in_sizes[0] / (NNEI * ED);

    cudaFuncSetAttribute(nwa_kernel, cudaFuncAttributeMaxDynamicSharedMemorySize,
                         SMEM_FLOATS * sizeof(float));
    nwa_kernel<<<B, NTHREADS, SMEM_FLOATS * sizeof(float)>>>(
        G, mk, r, in_w, in_b, out_w, out_b, ln_g, ln_b, out);
}

// round 12
// speedup vs baseline: 3.6652x; 2.5897x over previous
#include <cuda_runtime.h>
#include <math.h>
#include <stdint.h>

#define L_LAYERS 2
#define NNEI 120
#define ED 64
#define HD 128
#define FDIM 384
#define NTHREADS 1024
#define SCALING 0.08838834764831845f   // HD^-0.5
#define LN_EPS 1e-5f

// row strides (floats) chosen for conflict-free scalar fragment access
#define SXS 68
#define SQS 132
#define SKS 132
#define SVS 136

// shared layout (floats)
#define OFF_SX   0                     // 120*68  = 8160
#define OFF_SQ   8160                  // 120*132 = 15840 (q, later o)
#define OFF_SK   24000                 // 120*132 = 15840 (k, later aw logits)
#define OFF_SV   39840                 // 120*136 = 16320 (v, later D+out_b scratch)
#define OFF_R    56160                 // 120*3 = 360
#define OFF_MASK 56520                 // 120
#define SMEM_FLOATS 56768              // incl. tail pad; 227072 B <= 232448

__device__ __forceinline__ uint32_t f2t(float f) {
    uint32_t r; asm("cvt.rna.tf32.f32 %0, %1;" : "=r"(r) : "f"(f)); return r;
}
__device__ __forceinline__ void mma8(float c[4], const uint32_t a[4], const uint32_t b[2]) {
    asm("mma.sync.aligned.m16n8k8.row.col.f32.tf32.tf32.f32 "
        "{%0,%1,%2,%3},{%4,%5,%6,%7},{%8,%9},{%0,%1,%2,%3};"
        : "+f"(c[0]), "+f"(c[1]), "+f"(c[2]), "+f"(c[3])
        : "r"(a[0]), "r"(a[1]), "r"(a[2]), "r"(a[3]), "r"(b[0]), "r"(b[1]));
}

__device__ __forceinline__ float warp_sum(float v) {
    #pragma unroll
    for (int o = 16; o; o >>= 1) v += __shfl_xor_sync(0xffffffffu, v, o);
    return v;
}
__device__ __forceinline__ float warp_max(float v) {
    #pragma unroll
    for (int o = 16; o; o >>= 1) v = fmaxf(v, __shfl_xor_sync(0xffffffffu, v, o));
    return v;
}

__global__ __launch_bounds__(NTHREADS, 1)
void nwa_kernel(const float* __restrict__ G,
                const int* __restrict__ maskp,
                const float* __restrict__ rp,
                const float* __restrict__ in_w, const float* __restrict__ in_b,
                const float* __restrict__ out_w, const float* __restrict__ out_b,
                const float* __restrict__ ln_g, const float* __restrict__ ln_b,
                float* __restrict__ out)
{
    extern __shared__ float sm[];
    float* sx    = sm + OFF_SX;
    float* sq    = sm + OFF_SQ;
    float* sk    = sm + OFF_SK;
    float* sv    = sm + OFF_SV;
    float* sr    = sm + OFF_R;
    float* smask = sm + OFF_MASK;

    const int b = blockIdx.x;
    const int tid = threadIdx.x;
    const int w = tid >> 5;
    const int lane = tid & 31;
    const int g = lane >> 2;     // 0..7
    const int c = lane & 3;      // 0..3

    // ---- load per-batch inputs ----
    {
        const float4* Gx = (const float4*)(G + (size_t)b * NNEI * ED);
        float4* sx4 = (float4*)sx;
        for (int i = tid; i < NNEI * ED / 4; i += NTHREADS) {
            int n = i >> 4, j = i & 15;
            sx4[n * (SXS / 4) + j] = Gx[i];
        }
        const float* rb = rp + (size_t)b * NNEI * 3;
        for (int i = tid; i < NNEI * 3; i += NTHREADS) sr[i] = rb[i];
        if (tid < NNEI) smask[tid] = maskp[(size_t)b * NNEI + tid] ? 1.0f : 0.0f;
    }
    __syncthreads();

    for (int l = 0; l < L_LAYERS; l++) {
        // ===== Phase A: qkv^T[384x120] = W^T[384x64] @ x^T[64x120] =====
        // 24 warps, warp w = m-tile (16 f-rows); W frags direct from GMEM (L2-hot)
        const float* IW = in_w + (size_t)l * ED * FDIM;
        if (w < 24) {
            const int f0 = w * 16;
            uint32_t A[8][4];
            #pragma unroll
            for (int ks = 0; ks < 8; ks++) {
                int e0 = ks * 8;
                A[ks][0] = f2t(IW[(e0 + c) * FDIM + f0 + g]);
                A[ks][1] = f2t(IW[(e0 + c) * FDIM + f0 + g + 8]);
                A[ks][2] = f2t(IW[(e0 + c + 4) * FDIM + f0 + g]);
                A[ks][3] = f2t(IW[(e0 + c + 4) * FDIM + f0 + g + 8]);
            }
            float bv0 = in_b[l * FDIM + f0 + g];
            float bv1 = in_b[l * FDIM + f0 + g + 8];
            float* dst; int fofs, ds;
            if (w < 8)       { dst = sq; fofs = f0;       ds = SQS; }
            else if (w < 16) { dst = sk; fofs = f0 - 128; ds = SKS; }
            else             { dst = sv; fofs = f0 - 256; ds = SVS; }
            for (int nt = 0; nt < 15; nt++) {
                float C[4] = {0.f, 0.f, 0.f, 0.f};
                #pragma unroll
                for (int ks = 0; ks < 8; ks++) {
                    const float* xb = sx + (nt * 8 + g) * SXS + ks * 8;
                    uint32_t B[2];
                    B[0] = f2t(xb[c]); B[1] = f2t(xb[c + 4]);
                    mma8(C, A[ks], B);
                }
                int n0 = nt * 8 + 2 * c;
                dst[(n0    ) * ds + fofs + g    ] = C[0] + bv0;
                dst[(n0 + 1) * ds + fofs + g    ] = C[1] + bv0;
                dst[(n0    ) * ds + fofs + g + 8] = C[2] + bv1;
                dst[(n0 + 1) * ds + fofs + g + 8] = C[3] + bv1;
            }
        }
        __syncthreads();

        // ===== Phase B: l2norm rows of q, k, v =====
        for (int task = w; task < 3 * NNEI; task += 32) {
            int type = task / NNEI;
            int n = task - type * NNEI;
            float* base = (type == 0) ? (sq + n * SQS)
                        : (type == 1) ? (sk + n * SKS)
                                      : (sv + n * SVS);
            float4 vv = *(float4*)(base + 4 * lane);
            float s = vv.x * vv.x + vv.y * vv.y + vv.z * vv.z + vv.w * vv.w;
            s = warp_sum(s);
            float sc = 1.0f / fmaxf(sqrtf(s), 1e-12f);
            if (type == 0) sc *= SCALING;
            vv.x *= sc; vv.y *= sc; vv.z *= sc; vv.w *= sc;
            *(float4*)(base + 4 * lane) = vv;
        }
        __syncthreads();

        // ===== QK^T: logits[n][m], 120 tiles (8 mt x 15 nt), C held in regs =====
        float Cq[4][4];
        #pragma unroll
        for (int i = 0; i < 4; i++) {
            int t = w + 32 * i;
            if (t < 120) {
                int mt = t / 15, nt = t - mt * 15;
                float* C = Cq[i];
                C[0] = C[1] = C[2] = C[3] = 0.f;
                #pragma unroll
                for (int ks = 0; ks < 16; ks++) {
                    uint32_t A[4], B[2];
                    int h0 = ks * 8, r0 = mt * 16;
                    A[0] = f2t(sq[(r0 + g    ) * SQS + h0 + c]);
                    A[1] = f2t(sq[(r0 + g + 8) * SQS + h0 + c]);
                    A[2] = f2t(sq[(r0 + g    ) * SQS + h0 + c + 4]);
                    A[3] = f2t(sq[(r0 + g + 8) * SQS + h0 + c + 4]);
                    B[0] = f2t(sk[(nt * 8 + g) * SKS + h0 + c]);
                    B[1] = f2t(sk[(nt * 8 + g) * SKS + h0 + c + 4]);
                    mma8(C, A, B);
                }
            }
        }
        __syncthreads();   // all k reads done; sk becomes aw
        float* aw = sk;
        #pragma unroll
        for (int i = 0; i < 4; i++) {
            int t = w + 32 * i;
            if (t < 120) {
                int mt = t / 15, nt = t - mt * 15;
                int nr = mt * 16 + g, m0 = nt * 8 + 2 * c;
                aw[nr * SKS + m0    ] = Cq[i][0];
                aw[nr * SKS + m0 + 1] = Cq[i][1];
                if (nr + 8 < NNEI) {
                    aw[(nr + 8) * SKS + m0    ] = Cq[i][2];
                    aw[(nr + 8) * SKS + m0 + 1] = Cq[i][3];
                }
            }
        }
        __syncthreads();

        // ===== softmax + mask + angle (30 warps x 4 rows), in-place on aw =====
        if (w < 30) {
            #pragma unroll
            for (int r = 0; r < 4; r++) {
                int n = 4 * w + r;
                float4 a4 = *(float4*)(aw + n * SKS + 4 * lane);
                float lg[4] = {a4.x, a4.y, a4.z, a4.w};
                float mx = -1e30f;
                #pragma unroll
                for (int j = 0; j < 4; j++) {
                    int m = 4 * lane + j;
                    int mc = (m < NNEI) ? m : 0;
                    bool ok = (m < NNEI) && (smask[mc] > 0.5f);
                    lg[j] = ok ? lg[j] : -1e30f;
                    mx = fmaxf(mx, lg[j]);
                }
                mx = warp_max(mx);
                float ex[4], ssum = 0.f;
                #pragma unroll
                for (int j = 0; j < 4; j++) { ex[j] = __expf(lg[j] - mx); ssum += ex[j]; }
                ssum = warp_sum(ssum);
                float coef = smask[n] / ssum;
                float rn0 = sr[n * 3], rn1 = sr[n * 3 + 1], rn2 = sr[n * 3 + 2];
                float pv[4];
                #pragma unroll
                for (int j = 0; j < 4; j++) {
                    int m = 4 * lane + j;
                    int mc = (m < NNEI) ? m : 0;
                    float ang = rn0 * sr[mc * 3] + rn1 * sr[mc * 3 + 1] + rn2 * sr[mc * 3 + 2];
                    pv[j] = (m < NNEI) ? ex[j] * coef * ang : 0.f;
                }
                *(float4*)(aw + n * SKS + 4 * lane) = make_float4(pv[0], pv[1], pv[2], pv[3]);
            }
        }
        __syncthreads();

        // ===== AV: o[n][hd] = aw @ v, 128 tiles (8 mt x 16 nt), K = 120 (15 ks) =====
        #pragma unroll
        for (int i = 0; i < 4; i++) {
            int t = w + 32 * i;
            int mt = t >> 4, nt = t & 15;
            float C[4] = {0.f, 0.f, 0.f, 0.f};
            #pragma unroll
            for (int ks = 0; ks < 15; ks++) {
                uint32_t A[4], B[2];
                int m0 = ks * 8, r0 = mt * 16;
                A[0] = f2t(aw[(r0 + g    ) * SKS + m0 + c]);
                A[1] = f2t(aw[(r0 + g + 8) * SKS + m0 + c]);
                A[2] = f2t(aw[(r0 + g    ) * SKS + m0 + c + 4]);
                A[3] = f2t(aw[(r0 + g + 8) * SKS + m0 + c + 4]);
                B[0] = f2t(sv[(m0 + c    ) * SVS + nt * 8 + g]);
                B[1] = f2t(sv[(m0 + c + 4) * SVS + nt * 8 + g]);
                mma8(C, A, B);
            }
            int nr = mt * 16 + g, h0 = nt * 8 + 2 * c;
            sq[nr * SQS + h0    ] = C[0];          // o overwrites q
            sq[nr * SQS + h0 + 1] = C[1];
            if (nr + 8 < NNEI) {
                sq[(nr + 8) * SQS + h0    ] = C[2];
                sq[(nr + 8) * SQS + h0 + 1] = C[3];
            }
        }
        __syncthreads();

        // ===== Phase F: D[n][e] = o @ out_w (+ out_b), 64 tiles, scratch -> sv =====
        const float* OW = out_w + (size_t)l * HD * ED;
        #pragma unroll
        for (int i = 0; i < 2; i++) {
            int t = w + 32 * i;
            int mt = t >> 3, nt = t & 7;
            float C[4] = {0.f, 0.f, 0.f, 0.f};
            #pragma unroll
            for (int ks = 0; ks < 16; ks++) {
                uint32_t A[4], B[2];
                int h0 = ks * 8, r0 = mt * 16;
                A[0] = f2t(sq[(r0 + g    ) * SQS + h0 + c]);
                A[1] = f2t(sq[(r0 + g + 8) * SQS + h0 + c]);
                A[2] = f2t(sq[(r0 + g    ) * SQS + h0 + c + 4]);
                A[3] = f2t(sq[(r0 + g + 8) * SQS + h0 + c + 4]);
                B[0] = f2t(OW[(h0 + c    ) * ED + nt * 8 + g]);
                B[1] = f2t(OW[(h0 + c + 4) * ED + nt * 8 + g]);
                mma8(C, A, B);
            }
            int nr = mt * 16 + g, e0 = nt * 8 + 2 * c;
            float ob0 = out_b[l * ED + e0], ob1 = out_b[l * ED + e0 + 1];
            sv[nr * SVS + e0    ] = C[0] + ob0;
            sv[nr * SVS + e0 + 1] = C[1] + ob1;
            if (nr + 8 < NNEI) {
                sv[(nr + 8) * SVS + e0    ] = C[2] + ob0;
                sv[(nr + 8) * SVS + e0 + 1] = C[3] + ob1;
            }
        }
        __syncthreads();

        // ===== LN: x = LN(residual + D) (30 warps x 4 rows) =====
        if (w < 30) {
            float2 g2 = *(const float2*)(ln_g + l * ED + 2 * lane);
            float2 b2 = *(const float2*)(ln_b + l * ED + 2 * lane);
            #pragma unroll
            for (int r = 0; r < 4; r++) {
                int n = 4 * w + r;
                float2 dv  = *(float2*)(sv + n * SVS + 2 * lane);
                float2 res = *(float2*)(sx + n * SXS + 2 * lane);
                float x0 = res.x + dv.x, x1 = res.y + dv.y;
                float mu = warp_sum(x0 + x1) * (1.0f / 64.0f);
                float d0 = x0 - mu, d1 = x1 - mu;
                float var = warp_sum(d0 * d0 + d1 * d1) * (1.0f / 64.0f);
                float rs = rsqrtf(var + LN_EPS);
                float2 o2 = make_float2(d0 * rs * g2.x + b2.x, d1 * rs * g2.y + b2.y);
                *(float2*)(sx + n * SXS + 2 * lane) = o2;
            }
        }
        __syncthreads();
    }

    // ---- write output ----
    {
        float4* outp = (float4*)(out + (size_t)b * NNEI * ED);
        const float4* sx4 = (const float4*)sx;
        for (int i = tid; i < NNEI * ED / 4; i += NTHREADS) {
            int n = i >> 4, j = i & 15;
            outp[i] = sx4[n * (SXS / 4) + j];
        }
    }
}

extern "C" void kernel_launch(void* const* d_in, const int* in_sizes, int n_in,
                              void* d_out, int out_size) {
    const float* G     = (const float*)d_in[0];
    const int* mk      = (const int*)d_in[1];
    const float* r     = (const float*)d_in[2];
    const float* in_w  = (const float*)d_in[3];
    const float* in_b  = (const float*)d_in[4];
    const float* out_w = (const float*)d_in[5];
    const float* out_b = (const float*)d_in[6];
    const float* ln_g  = (const float*)d_in[7];
    const float* ln_b  = (const float*)d_in[8];
    float* out         = (float*)d_out;

    int B = in_sizes[0] / (NNEI * ED);

    cudaFuncSetAttribute(nwa_kernel, cudaFuncAttributeMaxDynamicSharedMemorySize,
                         SMEM_FLOATS * sizeof(float));
    nwa_kernel<<<B, NTHREADS, SMEM_FLOATS * sizeof(float)>>>(
        G, mk, r, in_w, in_b, out_w, out_b, ln_g, ln_b, out);
}

// round 15
// speedup vs baseline: 4.0790x; 1.1129x over previous
#include <cuda_runtime.h>
#include <math.h>
#include <stdint.h>

#define L_LAYERS 2
#define NNEI 120
#define ED 64
#define HD 128
#define FDIM 384
#define NTHREADS 1024
#define SCALING 0.08838834764831845f   // HD^-0.5
#define LN_EPS 1e-5f

// row strides (floats) chosen for conflict-free scalar fragment access
#define SXS 68
#define SQS 132
#define SKS 132
#define SVS 136

// shared layout (floats)
#define OFF_SX   0                     // 120*68  = 8160
#define OFF_SQ   8160                  // 120*132 = 15840 (q tf32; later o tf32)
#define OFF_SK   24000                 // 120*132 = 15840 (k tf32; later aw)
#define OFF_SV   39840                 // 120*136 = 16320 (v tf32; later D fp32)
#define OFF_R    56160                 // 120*3 = 360
#define OFF_MASK 56520                 // 120
#define SMEM_FLOATS 56768              // 227072 B <= 232448

__device__ __forceinline__ uint32_t f2t(float f) {
    uint32_t r; asm("cvt.rna.tf32.f32 %0, %1;" : "=r"(r) : "f"(f)); return r;
}
__device__ __forceinline__ void mma8(float c[4], const uint32_t a[4], const uint32_t b[2]) {
    asm("mma.sync.aligned.m16n8k8.row.col.f32.tf32.tf32.f32 "
        "{%0,%1,%2,%3},{%4,%5,%6,%7},{%8,%9},{%0,%1,%2,%3};"
        : "+f"(c[0]), "+f"(c[1]), "+f"(c[2]), "+f"(c[3])
        : "r"(a[0]), "r"(a[1]), "r"(a[2]), "r"(a[3]), "r"(b[0]), "r"(b[1]));
}
__device__ __forceinline__ uint32_t ldu(const float* p) {
    return *(const uint32_t*)p;
}

__device__ __forceinline__ float warp_sum(float v) {
    #pragma unroll
    for (int o = 16; o; o >>= 1) v += __shfl_xor_sync(0xffffffffu, v, o);
    return v;
}
__device__ __forceinline__ float warp_max(float v) {
    #pragma unroll
    for (int o = 16; o; o >>= 1) v = fmaxf(v, __shfl_xor_sync(0xffffffffu, v, o));
    return v;
}

__global__ __launch_bounds__(NTHREADS, 1)
void nwa_kernel(const float* __restrict__ G,
                const int* __restrict__ maskp,
                const float* __restrict__ rp,
                const float* __restrict__ in_w, const float* __restrict__ in_b,
                const float* __restrict__ out_w, const float* __restrict__ out_b,
                const float* __restrict__ ln_g, const float* __restrict__ ln_b,
                float* __restrict__ out)
{
    extern __shared__ float sm[];
    float* sx    = sm + OFF_SX;
    float* sq    = sm + OFF_SQ;
    float* sk    = sm + OFF_SK;
    float* sv    = sm + OFF_SV;
    float* sr    = sm + OFF_R;
    float* smask = sm + OFF_MASK;

    const int b = blockIdx.x;
    const int tid = threadIdx.x;
    const int w = tid >> 5;
    const int lane = tid & 31;
    const int g = lane >> 2;     // 0..7
    const int c = lane & 3;      // 0..3

    // ---- load per-batch inputs ----
    {
        const float4* Gx = (const float4*)(G + (size_t)b * NNEI * ED);
        float4* sx4 = (float4*)sx;
        for (int i = tid; i < NNEI * ED / 4; i += NTHREADS) {
            int n = i >> 4, j = i & 15;
            sx4[n * (SXS / 4) + j] = Gx[i];
        }
        const float* rb = rp + (size_t)b * NNEI * 3;
        for (int i = tid; i < NNEI * 3; i += NTHREADS) sr[i] = rb[i];
        if (tid < NNEI) smask[tid] = maskp[(size_t)b * NNEI + tid] ? 1.0f : 0.0f;
    }
    __syncthreads();

    for (int l = 0; l < L_LAYERS; l++) {
        // ===== Phase A: qkv^T = W^T @ x^T (24 warps; W frags from GMEM, reused over nt) =====
        const float* IW = in_w + (size_t)l * ED * FDIM;
        if (w < 24) {
            const int f0 = w * 16;
            uint32_t A[8][4];
            #pragma unroll
            for (int ks = 0; ks < 8; ks++) {
                int e0 = ks * 8;
                A[ks][0] = f2t(IW[(e0 + c) * FDIM + f0 + g]);
                A[ks][1] = f2t(IW[(e0 + c) * FDIM + f0 + g + 8]);
                A[ks][2] = f2t(IW[(e0 + c + 4) * FDIM + f0 + g]);
                A[ks][3] = f2t(IW[(e0 + c + 4) * FDIM + f0 + g + 8]);
            }
            float bv0 = in_b[l * FDIM + f0 + g];
            float bv1 = in_b[l * FDIM + f0 + g + 8];
            float* dst; int fofs, ds;
            if (w < 8)       { dst = sq; fofs = f0;       ds = SQS; }
            else if (w < 16) { dst = sk; fofs = f0 - 128; ds = SKS; }
            else             { dst = sv; fofs = f0 - 256; ds = SVS; }
            for (int nt = 0; nt < 15; nt++) {
                float C[4] = {0.f, 0.f, 0.f, 0.f};
                #pragma unroll
                for (int ks = 0; ks < 8; ks++) {
                    const float* xb = sx + (nt * 8 + g) * SXS + ks * 8;
                    uint32_t B[2];
                    B[0] = f2t(xb[c]); B[1] = f2t(xb[c + 4]);
                    mma8(C, A[ks], B);
                }
                int n0 = nt * 8 + 2 * c;
                dst[(n0    ) * ds + fofs + g    ] = C[0] + bv0;
                dst[(n0 + 1) * ds + fofs + g    ] = C[1] + bv0;
                dst[(n0    ) * ds + fofs + g + 8] = C[2] + bv1;
                dst[(n0 + 1) * ds + fofs + g + 8] = C[3] + bv1;
            }
        }
        __syncthreads();

        // ===== Phase B: l2norm rows of q, k, v; write back tf32 bits =====
        for (int task = w; task < 3 * NNEI; task += 32) {
            int type = task / NNEI;
            int n = task - type * NNEI;
            float* base = (type == 0) ? (sq + n * SQS)
                        : (type == 1) ? (sk + n * SKS)
                                      : (sv + n * SVS);
            float4 vv = *(float4*)(base + 4 * lane);
            float s = vv.x * vv.x + vv.y * vv.y + vv.z * vv.z + vv.w * vv.w;
            s = warp_sum(s);
            float sc = 1.0f / fmaxf(sqrtf(s), 1e-12f);
            if (type == 0) sc *= SCALING;
            uint4 tv = make_uint4(f2t(vv.x * sc), f2t(vv.y * sc),
                                  f2t(vv.z * sc), f2t(vv.w * sc));
            *(uint4*)(base + 4 * lane) = tv;
        }
        __syncthreads();

        // ===== QK^T: warp = (mt = w>>2, nt = (w&3)+4j); A (q) reused 4x =====
        float Cq[4][4];
        {
            const int mt = w >> 2, ntb = w & 3, r0 = mt * 16;
            #pragma unroll
            for (int j = 0; j < 4; j++)
                Cq[j][0] = Cq[j][1] = Cq[j][2] = Cq[j][3] = 0.f;
            #pragma unroll 4
            for (int ks = 0; ks < 16; ks++) {
                int h0 = ks * 8;
                uint32_t A[4];
                A[0] = ldu(sq + (r0 + g    ) * SQS + h0 + c);
                A[1] = ldu(sq + (r0 + g + 8) * SQS + h0 + c);
                A[2] = ldu(sq + (r0 + g    ) * SQS + h0 + c + 4);
                A[3] = ldu(sq + (r0 + g + 8) * SQS + h0 + c + 4);
                #pragma unroll
                for (int j = 0; j < 4; j++) {
                    int nt = ntb + 4 * j;
                    if (nt < 15) {
                        uint32_t B[2];
                        B[0] = ldu(sk + (nt * 8 + g) * SKS + h0 + c);
                        B[1] = ldu(sk + (nt * 8 + g) * SKS + h0 + c + 4);
                        mma8(Cq[j], A, B);
                    }
                }
            }
        }
        __syncthreads();   // all k reads done; sk becomes aw
        float* aw = sk;
        {
            const int mt = w >> 2, ntb = w & 3;
            int nr = mt * 16 + g;
            #pragma unroll
            for (int j = 0; j < 4; j++) {
                int nt = ntb + 4 * j;
                if (nt < 15) {
                    int m0 = nt * 8 + 2 * c;
                    *(float2*)(aw + nr * SKS + m0) = make_float2(Cq[j][0], Cq[j][1]);
                    if (nr + 8 < NNEI)
                        *(float2*)(aw + (nr + 8) * SKS + m0) = make_float2(Cq[j][2], Cq[j][3]);
                }
            }
        }
        __syncthreads();

        // ===== softmax + mask + angle; write aw back as tf32 bits =====
        if (w < 30) {
            #pragma unroll
            for (int r = 0; r < 4; r++) {
                int n = 4 * w + r;
                float4 a4 = *(float4*)(aw + n * SKS + 4 * lane);
                float lg[4] = {a4.x, a4.y, a4.z, a4.w};
                float mx = -1e30f;
                #pragma unroll
                for (int j = 0; j < 4; j++) {
                    int m = 4 * lane + j;
                    int mc = (m < NNEI) ? m : 0;
                    bool ok = (m < NNEI) && (smask[mc] > 0.5f);
                    lg[j] = ok ? lg[j] : -1e30f;
                    mx = fmaxf(mx, lg[j]);
                }
                mx = warp_max(mx);
                float ex[4], ssum = 0.f;
                #pragma unroll
                for (int j = 0; j < 4; j++) { ex[j] = __expf(lg[j] - mx); ssum += ex[j]; }
                ssum = warp_sum(ssum);
                float coef = smask[n] / ssum;
                float rn0 = sr[n * 3], rn1 = sr[n * 3 + 1], rn2 = sr[n * 3 + 2];
                uint32_t pv[4];
                #pragma unroll
                for (int j = 0; j < 4; j++) {
                    int m = 4 * lane + j;
                    int mc = (m < NNEI) ? m : 0;
                    float ang = rn0 * sr[mc * 3] + rn1 * sr[mc * 3 + 1] + rn2 * sr[mc * 3 + 2];
                    pv[j] = f2t((m < NNEI) ? ex[j] * coef * ang : 0.f);
                }
                *(uint4*)(aw + n * SKS + 4 * lane) = make_uint4(pv[0], pv[1], pv[2], pv[3]);
            }
        }
        __syncthreads();

        // ===== AV: warp = (mt = w>>2, nt = (w&3)+4j); A (aw) reused 4x; o -> sq tf32 =====
        {
            const int mt = w >> 2, ntb = w & 3, r0 = mt * 16;
            float C[4][4];
            #pragma unroll
            for (int j = 0; j < 4; j++)
                C[j][0] = C[j][1] = C[j][2] = C[j][3] = 0.f;
            #pragma unroll 3
            for (int ks = 0; ks < 15; ks++) {
                int m0 = ks * 8;
                uint32_t A[4];
                A[0] = ldu(aw + (r0 + g    ) * SKS + m0 + c);
                A[1] = ldu(aw + (r0 + g + 8) * SKS + m0 + c);
                A[2] = ldu(aw + (r0 + g    ) * SKS + m0 + c + 4);
                A[3] = ldu(aw + (r0 + g + 8) * SKS + m0 + c + 4);
                #pragma unroll
                for (int j = 0; j < 4; j++) {
                    int nt = ntb + 4 * j;
                    uint32_t B[2];
                    B[0] = ldu(sv + (m0 + c    ) * SVS + nt * 8 + g);
                    B[1] = ldu(sv + (m0 + c + 4) * SVS + nt * 8 + g);
                    mma8(C[j], A, B);
                }
            }
            int nr = r0 + g;
            #pragma unroll
            for (int j = 0; j < 4; j++) {
                int h0 = (ntb + 4 * j) * 8 + 2 * c;
                *(uint2*)(sq + nr * SQS + h0) = make_uint2(f2t(C[j][0]), f2t(C[j][1]));
                if (nr + 8 < NNEI)
                    *(uint2*)(sq + (nr + 8) * SQS + h0) = make_uint2(f2t(C[j][2]), f2t(C[j][3]));
            }
        }
        __syncthreads();

        // ===== Phase F: D = o @ out_w + out_b (fp32 into sv); A (o) reused 2x =====
        const float* OW = out_w + (size_t)l * HD * ED;
        {
            const int mt = w >> 2, ntb = w & 3, r0 = mt * 16;
            float C[2][4];
            #pragma unroll
            for (int j = 0; j < 2; j++)
                C[j][0] = C[j][1] = C[j][2] = C[j][3] = 0.f;
            #pragma unroll 4
            for (int ks = 0; ks < 16; ks++) {
                int h0 = ks * 8;
                uint32_t A[4];
                A[0] = ldu(sq + (r0 + g    ) * SQS + h0 + c);
                A[1] = ldu(sq + (r0 + g + 8) * SQS + h0 + c);
                A[2] = ldu(sq + (r0 + g    ) * SQS + h0 + c + 4);
                A[3] = ldu(sq + (r0 + g + 8) * SQS + h0 + c + 4);
                #pragma unroll
                for (int j = 0; j < 2; j++) {
                    int nt = ntb + 4 * j;
                    uint32_t B[2];
                    B[0] = f2t(OW[(h0 + c    ) * ED + nt * 8 + g]);
                    B[1] = f2t(OW[(h0 + c + 4) * ED + nt * 8 + g]);
                    mma8(C[j], A, B);
                }
            }
            int nr = r0 + g;
            #pragma unroll
            for (int j = 0; j < 2; j++) {
                int e0 = (ntb + 4 * j) * 8 + 2 * c;
                float ob0 = out_b[l * ED + e0], ob1 = out_b[l * ED + e0 + 1];
                *(float2*)(sv + nr * SVS + e0) = make_float2(C[j][0] + ob0, C[j][1] + ob1);
                if (nr + 8 < NNEI)
                    *(float2*)(sv + (nr + 8) * SVS + e0) =
                        make_float2(C[j][2] + ob0, C[j][3] + ob1);
            }
        }
        __syncthreads();

        // ===== LN: x = LN(residual + D) (30 warps x 4 rows) =====
        if (w < 30) {
            float2 g2 = *(const float2*)(ln_g + l * ED + 2 * lane);
            float2 b2 = *(const float2*)(ln_b + l * ED + 2 * lane);
            #pragma unroll
            for (int r = 0; r < 4; r++) {
                int n = 4 * w + r;
                float2 dv  = *(float2*)(sv + n * SVS + 2 * lane);
                float2 res = *(float2*)(sx + n * SXS + 2 * lane);
                float x0 = res.x + dv.x, x1 = res.y + dv.y;
                float mu = warp_sum(x0 + x1) * (1.0f / 64.0f);
                float d0 = x0 - mu, d1 = x1 - mu;
                float var = warp_sum(d0 * d0 + d1 * d1) * (1.0f / 64.0f);
                float rs = rsqrtf(var + LN_EPS);
                float2 o2 = make_float2(d0 * rs * g2.x + b2.x, d1 * rs * g2.y + b2.y);
                *(float2*)(sx + n * SXS + 2 * lane) = o2;
            }
        }
        __syncthreads();
    }

    // ---- write output ----
    {
        float4* outp = (float4*)(out + (size_t)b * NNEI * ED);
        const float4* sx4 = (const float4*)sx;
        for (int i = tid; i < NNEI * ED / 4; i += NTHREADS) {
            int n = i >> 4, j = i & 15;
            outp[i] = sx4[n * (SXS / 4) + j];
        }
    }
}

extern "C" void kernel_launch(void* const* d_in, const int* in_sizes, int n_in,
                              void* d_out, int out_size) {
    const float* G     = (const float*)d_in[0];
    const int* mk      = (const int*)d_in[1];
    const float* r     = (const float*)d_in[2];
    const float* in_w  = (const float*)d_in[3];
    const float* in_b  = (const float*)d_in[4];
    const float* out_w = (const float*)d_in[5];
    const float* out_b = (const float*)d_in[6];
    const float* ln_g  = (const float*)d_in[7];
    const float* ln_b  = (const float*)d_in[8];
    float* out         = (float*)d_out;

    int B = in_sizes[0] / (NNEI * ED);

    cudaFuncSetAttribute(nwa_kernel, cudaFuncAttributeMaxDynamicSharedMemorySize,
                         SMEM_FLOATS * sizeof(float));
    nwa_kernel<<<B, NTHREADS, SMEM_FLOATS * sizeof(float)>>>(
        G, mk, r, in_w, in_b, out_w, out_b, ln_g, ln_b, out);
}

// round 17
// speedup vs baseline: 5.5213x; 1.3536x over previous
#include <cuda_runtime.h>
#include <cuda_bf16.h>
#include <math.h>
#include <stdint.h>

#define L_LAYERS 2
#define NNEI 120
#define ED 64
#define HD 128
#define FDIM 384
#define NTHREADS 1024
#define SCALING 0.08838834764831845f   // HD^-0.5
#define LN_EPS 1e-5f

// strides in 32-bit words
#define SXS  68   // sx fp32 rows (64 data)
#define SXBS 36   // x bf16-pairs rows (32 data words)
#define SQS  68   // q/o bf16-pairs rows (64 data words)
#define SKS  68   // k, later aw (60 data words + 4 pad)
#define SVS  68   // svT rows h, m-pairs (60 data + 4 pad)
#define DSS  68   // D fp32 rows
#define VPS  17

// region offsets in 4-byte units
#define OFF_SX    0        // 120*68  = 8160
#define OFF_SXB   8160     // 120*36  = 4320
#define OFF_SQ    12480    // 120*68  = 8160
#define OFF_SK    20640    // 120*68  = 8160
#define OFF_SVT   28800    // 128*68  = 8704
#define OFF_WBUF  37504    // 12288 (wfrag; later owfrag[0:4096) + D)
#define OFF_OWF   37504
#define OFF_D     41600    // 120*68 fp32 = 8160 (ends 49760)
#define OFF_VPART 49792    // 128*17 = 2176
#define OFF_R     51968    // 360
#define OFF_MASK  52328    // 120
#define OFF_VINV  52448    // 120 (+pad)
#define SMEM_FLOATS 52576  // 210304 B <= 232448

__device__ __forceinline__ uint32_t pkbf2(float lo, float hi) {
    uint32_t d;
    asm("cvt.rn.bf16x2.f32 %0, %1, %2;" : "=r"(d) : "f"(hi), "f"(lo));
    return d;
}
__device__ __forceinline__ float2 upbf2(uint32_t u) {
    return make_float2(__uint_as_float(u << 16),
                       __uint_as_float(u & 0xffff0000u));
}
__device__ __forceinline__ void mmabf(float c[4], const uint32_t a[4],
                                      uint32_t b0, uint32_t b1) {
    asm("mma.sync.aligned.m16n8k16.row.col.f32.bf16.bf16.f32 "
        "{%0,%1,%2,%3},{%4,%5,%6,%7},{%8,%9},{%0,%1,%2,%3};"
        : "+f"(c[0]), "+f"(c[1]), "+f"(c[2]), "+f"(c[3])
        : "r"(a[0]), "r"(a[1]), "r"(a[2]), "r"(a[3]), "r"(b0), "r"(b1));
}

__device__ __forceinline__ float warp_sum(float v) {
    #pragma unroll
    for (int o = 16; o; o >>= 1) v += __shfl_xor_sync(0xffffffffu, v, o);
    return v;
}
__device__ __forceinline__ float warp_max(float v) {
    #pragma unroll
    for (int o = 16; o; o >>= 1) v = fmaxf(v, __shfl_xor_sync(0xffffffffu, v, o));
    return v;
}

__global__ __launch_bounds__(NTHREADS, 1)
void nwa_kernel(const float* __restrict__ G,
                const int* __restrict__ maskp,
                const float* __restrict__ rp,
                const float* __restrict__ in_w, const float* __restrict__ in_b,
                const float* __restrict__ out_w, const float* __restrict__ out_b,
                const float* __restrict__ ln_g, const float* __restrict__ ln_b,
                float* __restrict__ out)
{
    extern __shared__ float sm[];
    float* sx      = sm + OFF_SX;
    uint32_t* sxb  = (uint32_t*)(sm + OFF_SXB);
    uint32_t* q32  = (uint32_t*)(sm + OFF_SQ);
    uint32_t* k32  = (uint32_t*)(sm + OFF_SK);     // later aw
    uint32_t* v32  = (uint32_t*)(sm + OFF_SVT);
    float* Dm      = sm + OFF_D;
    float* vpart   = sm + OFF_VPART;
    float* sr      = sm + OFF_R;
    float* smask   = sm + OFF_MASK;
    float* vinv    = sm + OFF_VINV;

    const int b = blockIdx.x;
    const int tid = threadIdx.x;
    const int w = tid >> 5;
    const int lane = tid & 31;
    const int g = lane >> 2;
    const int c = lane & 3;

    // ---- load per-batch inputs (fp32 residual + bf16 copy) ----
    {
        const float4* Gx = (const float4*)(G + (size_t)b * NNEI * ED);
        float4* sx4 = (float4*)sx;
        for (int i = tid; i < NNEI * ED / 4; i += NTHREADS) {
            int n = i >> 4, j = i & 15;
            float4 gv = Gx[i];
            sx4[n * (SXS / 4) + j] = gv;
            sxb[n * SXBS + 2 * j    ] = pkbf2(gv.x, gv.y);
            sxb[n * SXBS + 2 * j + 1] = pkbf2(gv.z, gv.w);
        }
        const float* rb = rp + (size_t)b * NNEI * 3;
        for (int i = tid; i < NNEI * 3; i += NTHREADS) sr[i] = rb[i];
        if (tid < NNEI) smask[tid] = maskp[(size_t)b * NNEI + tid] ? 1.0f : 0.0f;
    }
    __syncthreads();

    for (int l = 0; l < L_LAYERS; l++) {
        const float* IW = in_w + (size_t)l * ED * FDIM;
        // ---- stage in_w in fragment order: wfrag[nt][ks][half][lane] ----
        {
            uint32_t* wf = (uint32_t*)(sm + OFF_WBUF);
            for (int idx = tid; idx < 12288; idx += NTHREADS) {
                int l2 = idx & 31, half = (idx >> 5) & 1, ks = (idx >> 6) & 3, nt = idx >> 8;
                int gg = l2 >> 2, cc = l2 & 3;
                int f = nt * 8 + gg, e = ks * 16 + 2 * cc + 8 * half;
                wf[idx] = pkbf2(IW[e * FDIM + f], IW[(e + 1) * FDIM + f]);
            }
        }
        __syncthreads();

        // ===== Phase A: qkv = x @ in_w + b  (M=120,N=384,K=64) =====
        {
            const uint32_t* wf = (const uint32_t*)(sm + OFF_WBUF);
            __nv_bfloat16* vbh = (__nv_bfloat16*)v32;
            const int mt = w >> 2, ntb = w & 3, r0 = mt * 16;
            uint32_t A[4][4];
            #pragma unroll
            for (int ks = 0; ks < 4; ks++) {
                A[ks][0] = sxb[(r0 + g    ) * SXBS + ks * 8 + c];
                A[ks][1] = sxb[(r0 + g + 8) * SXBS + ks * 8 + c];
                A[ks][2] = sxb[(r0 + g    ) * SXBS + ks * 8 + c + 4];
                A[ks][3] = sxb[(r0 + g + 8) * SXBS + ks * 8 + c + 4];
            }
            #pragma unroll 2
            for (int i = 0; i < 12; i++) {
                int nt = ntb + 4 * i;
                float C[4] = {0.f, 0.f, 0.f, 0.f};
                #pragma unroll
                for (int ks = 0; ks < 4; ks++) {
                    uint32_t b0 = wf[(nt * 4 + ks) * 64 + lane];
                    uint32_t b1 = wf[(nt * 4 + ks) * 64 + 32 + lane];
                    mmabf(C, A[ks], b0, b1);
                }
                float bv0 = in_b[l * FDIM + nt * 8 + 2 * c];
                float bv1 = in_b[l * FDIM + nt * 8 + 2 * c + 1];
                float d0 = C[0] + bv0, d1 = C[1] + bv1;
                float d2 = C[2] + bv0, d3 = C[3] + bv1;
                if (nt < 16) {
                    q32[(r0 + g) * SQS + nt * 4 + c] = pkbf2(d0, d1);
                    if (r0 + g + 8 < NNEI)
                        q32[(r0 + g + 8) * SQS + nt * 4 + c] = pkbf2(d2, d3);
                } else if (nt < 32) {
                    int ntl = nt - 16;
                    k32[(r0 + g) * SKS + ntl * 4 + c] = pkbf2(d0, d1);
                    if (r0 + g + 8 < NNEI)
                        k32[(r0 + g + 8) * SKS + ntl * 4 + c] = pkbf2(d2, d3);
                } else {
                    int h0 = (nt - 32) * 8 + 2 * c;
                    int m0 = r0 + g;
                    vbh[(h0    ) * (2 * SVS) + m0] = __float2bfloat16(d0);
                    vbh[(h0 + 1) * (2 * SVS) + m0] = __float2bfloat16(d1);
                    if (m0 + 8 < NNEI) {
                        vbh[(h0    ) * (2 * SVS) + m0 + 8] = __float2bfloat16(d2);
                        vbh[(h0 + 1) * (2 * SVS) + m0 + 8] = __float2bfloat16(d3);
                    }
                    float p0 = d0 * d0 + d1 * d1;
                    float p1 = d2 * d2 + d3 * d3;
                    p0 += __shfl_xor_sync(0xffffffffu, p0, 1);
                    p0 += __shfl_xor_sync(0xffffffffu, p0, 2);
                    p1 += __shfl_xor_sync(0xffffffffu, p1, 1);
                    p1 += __shfl_xor_sync(0xffffffffu, p1, 2);
                    if (c == 0) {
                        int t = 4 * ntb + (i - 8);
                        vpart[m0 * VPS + t] = p0;
                        vpart[(m0 + 8) * VPS + t] = p1;
                    }
                }
            }
        }
        __syncthreads();

        // ===== norms: q/k rows; v via vpart -> vinv; zero svT pads =====
        for (int task = w; task < 240; task += 32) {
            int ty = task >= 120 ? 1 : 0;
            int n = task - ty * 120;
            uint32_t* base = (ty ? k32 : q32) + n * SQS;
            uint2 u = *(uint2*)(base + 2 * lane);
            float2 a = upbf2(u.x), d = upbf2(u.y);
            float s = a.x * a.x + a.y * a.y + d.x * d.x + d.y * d.y;
            s = warp_sum(s);
            float sc = 1.0f / fmaxf(sqrtf(s), 1e-12f);
            if (!ty) sc *= SCALING;
            uint2 o;
            o.x = pkbf2(a.x * sc, a.y * sc);
            o.y = pkbf2(d.x * sc, d.y * sc);
            *(uint2*)(base + 2 * lane) = o;
        }
        if (tid < NNEI) {
            float s = 0.f;
            #pragma unroll
            for (int t = 0; t < 16; t++) s += vpart[tid * VPS + t];
            vinv[tid] = 1.0f / fmaxf(sqrtf(s), 1e-12f);
        }
        if (tid < 512) v32[(tid >> 2) * SVS + 60 + (tid & 3)] = 0u;
        __syncthreads();

        // ===== QK^T (M=120,N=120,K=128): warp=(mt=w>>2, nt=(w&3)+4j) =====
        float Cq[4][4];
        {
            const int mt = w >> 2, ntb = w & 3, r0 = mt * 16;
            #pragma unroll
            for (int j = 0; j < 4; j++)
                Cq[j][0] = Cq[j][1] = Cq[j][2] = Cq[j][3] = 0.f;
            #pragma unroll 2
            for (int ks = 0; ks < 8; ks++) {
                uint32_t A[4];
                A[0] = q32[(r0 + g    ) * SQS + ks * 8 + c];
                A[1] = q32[(r0 + g + 8) * SQS + ks * 8 + c];
                A[2] = q32[(r0 + g    ) * SQS + ks * 8 + c + 4];
                A[3] = q32[(r0 + g + 8) * SQS + ks * 8 + c + 4];
                #pragma unroll
                for (int j = 0; j < 4; j++) {
                    int nt = ntb + 4 * j;
                    if (nt < 15) {
                        uint32_t b0 = k32[(nt * 8 + g) * SKS + ks * 8 + c];
                        uint32_t b1 = k32[(nt * 8 + g) * SKS + ks * 8 + c + 4];
                        mmabf(Cq[j], A, b0, b1);
                    }
                }
            }
        }
        __syncthreads();   // k reads done; sk region becomes aw (bf16 pairs over m)
        {
            const int mt = w >> 2, ntb = w & 3, r0 = mt * 16;
            #pragma unroll
            for (int j = 0; j < 4; j++) {
                int nt = ntb + 4 * j;
                if (nt < 15) {
                    k32[(r0 + g) * SKS + nt * 4 + c] = pkbf2(Cq[j][0], Cq[j][1]);
                    if (r0 + g + 8 < NNEI)
                        k32[(r0 + g + 8) * SKS + nt * 4 + c] = pkbf2(Cq[j][2], Cq[j][3]);
                }
            }
        }
        __syncthreads();

        // ---- stage out_w frags + softmax (mask, angle, vinv fold) ----
        {
            const float* OW = out_w + (size_t)l * HD * ED;
            uint32_t* owf = (uint32_t*)(sm + OFF_OWF);
            for (int idx = tid; idx < 4096; idx += NTHREADS) {
                int l2 = idx & 31, half = (idx >> 5) & 1, ks = (idx >> 6) & 7, nt = idx >> 9;
                int gg = l2 >> 2, cc = l2 & 3;
                int e = nt * 8 + gg, h = ks * 16 + 2 * cc + 8 * half;
                owf[idx] = pkbf2(OW[h * ED + e], OW[(h + 1) * ED + e]);
            }
        }
        if (w < 30) {
            uint32_t* aw = k32;
            #pragma unroll
            for (int r = 0; r < 4; r++) {
                int n = 4 * w + r;
                uint2 u = *(uint2*)(aw + n * SKS + 2 * lane);
                float2 f01 = upbf2(u.x), f23 = upbf2(u.y);
                float lg[4] = {f01.x, f01.y, f23.x, f23.y};
                float mx = -1e30f;
                #pragma unroll
                for (int j = 0; j < 4; j++) {
                    int m = 4 * lane + j;
                    bool ok = (m < NNEI) && (smask[m < NNEI ? m : 0] > 0.5f);
                    lg[j] = ok ? lg[j] : -1e30f;
                    mx = fmaxf(mx, lg[j]);
                }
                mx = warp_max(mx);
                float ex[4], ssum = 0.f;
                #pragma unroll
                for (int j = 0; j < 4; j++) { ex[j] = __expf(lg[j] - mx); ssum += ex[j]; }
                ssum = warp_sum(ssum);
                float coef = smask[n] / ssum;
                float rn0 = sr[n * 3], rn1 = sr[n * 3 + 1], rn2 = sr[n * 3 + 2];
                float pv[4];
                #pragma unroll
                for (int j = 0; j < 4; j++) {
                    int m = 4 * lane + j;
                    int mc = (m < NNEI) ? m : 0;
                    float ang = rn0 * sr[mc * 3] + rn1 * sr[mc * 3 + 1] + rn2 * sr[mc * 3 + 2];
                    pv[j] = ex[j] * coef * ang * vinv[mc];   // masked/invalid -> ex==0
                }
                uint2 o;
                o.x = pkbf2(pv[0], pv[1]);
                o.y = pkbf2(pv[2], pv[3]);
                *(uint2*)(aw + n * SKS + 2 * lane) = o;   // lanes 30/31 zero the pads
            }
        }
        __syncthreads();

        // ===== AV (M=120,N=128,K=128 padded): o -> sq (bf16 pairs over h) =====
        {
            const uint32_t* aw = k32;
            const int mt = w >> 2, ntb = w & 3, r0 = mt * 16;
            float C[4][4];
            #pragma unroll
            for (int j = 0; j < 4; j++)
                C[j][0] = C[j][1] = C[j][2] = C[j][3] = 0.f;
            #pragma unroll 2
            for (int ks = 0; ks < 8; ks++) {
                uint32_t A[4];
                A[0] = aw[(r0 + g    ) * SKS + ks * 8 + c];
                A[1] = aw[(r0 + g + 8) * SKS + ks * 8 + c];
                A[2] = aw[(r0 + g    ) * SKS + ks * 8 + c + 4];
                A[3] = aw[(r0 + g + 8) * SKS + ks * 8 + c + 4];
                #pragma unroll
                for (int j = 0; j < 4; j++) {
                    int nt = ntb + 4 * j;
                    uint32_t b0 = v32[(nt * 8 + g) * SVS + ks * 8 + c];
                    uint32_t b1 = v32[(nt * 8 + g) * SVS + ks * 8 + c + 4];
                    mmabf(C[j], A, b0, b1);
                }
            }
            #pragma unroll
            for (int j = 0; j < 4; j++) {
                int nt = ntb + 4 * j;
                q32[(r0 + g) * SQS + nt * 4 + c] = pkbf2(C[j][0], C[j][1]);
                if (r0 + g + 8 < NNEI)
                    q32[(r0 + g + 8) * SQS + nt * 4 + c] = pkbf2(C[j][2], C[j][3]);
            }
        }
        __syncthreads();

        // ===== F: D = o @ out_w + out_b (fp32) =====
        {
            const uint32_t* owf = (const uint32_t*)(sm + OFF_OWF);
            const int mt = w >> 2, ntb = w & 3, r0 = mt * 16;
            float C[2][4];
            #pragma unroll
            for (int j = 0; j < 2; j++)
                C[j][0] = C[j][1] = C[j][2] = C[j][3] = 0.f;
            #pragma unroll 2
            for (int ks = 0; ks < 8; ks++) {
                uint32_t A[4];
                A[0] = q32[(r0 + g    ) * SQS + ks * 8 + c];
                A[1] = q32[(r0 + g + 8) * SQS + ks * 8 + c];
                A[2] = q32[(r0 + g    ) * SQS + ks * 8 + c + 4];
                A[3] = q32[(r0 + g + 8) * SQS + ks * 8 + c + 4];
                #pragma unroll
                for (int j = 0; j < 2; j++) {
                    int nt = ntb + 4 * j;
                    uint32_t b0 = owf[(nt * 8 + ks) * 64 + lane];
                    uint32_t b1 = owf[(nt * 8 + ks) * 64 + 32 + lane];
                    mmabf(C[j], A, b0, b1);
                }
            }
            #pragma unroll
            for (int j = 0; j < 2; j++) {
                int nt = ntb + 4 * j;
                int e0 = nt * 8 + 2 * c;
                float ob0 = out_b[l * ED + e0], ob1 = out_b[l * ED + e0 + 1];
                *(float2*)(Dm + (r0 + g) * DSS + e0) =
                    make_float2(C[j][0] + ob0, C[j][1] + ob1);
                if (r0 + g + 8 < NNEI)
                    *(float2*)(Dm + (r0 + g + 8) * DSS + e0) =
                        make_float2(C[j][2] + ob0, C[j][3] + ob1);
            }
        }
        __syncthreads();

        // ===== LN: x = LN(residual + D); refresh fp32 sx and bf16 sxb =====
        if (w < 30) {
            float2 g2 = *(const float2*)(ln_g + l * ED + 2 * lane);
            float2 b2 = *(const float2*)(ln_b + l * ED + 2 * lane);
            #pragma unroll
            for (int r = 0; r < 4; r++) {
                int n = 4 * w + r;
                float2 dv  = *(float2*)(Dm + n * DSS + 2 * lane);
                float2 res = *(float2*)(sx + n * SXS + 2 * lane);
                float x0 = res.x + dv.x, x1 = res.y + dv.y;
                float mu = warp_sum(x0 + x1) * (1.0f / 64.0f);
                float d0 = x0 - mu, d1 = x1 - mu;
                float var = warp_sum(d0 * d0 + d1 * d1) * (1.0f / 64.0f);
                float rs = rsqrtf(var + LN_EPS);
                float2 o2 = make_float2(d0 * rs * g2.x + b2.x, d1 * rs * g2.y + b2.y);
                *(float2*)(sx + n * SXS + 2 * lane) = o2;
                sxb[n * SXBS + lane] = pkbf2(o2.x, o2.y);
            }
        }
        __syncthreads();
    }

    // ---- write output ----
    {
        float4* outp = (float4*)(out + (size_t)b * NNEI * ED);
        const float4* sx4 = (const float4*)sx;
        for (int i = tid; i < NNEI * ED / 4; i += NTHREADS) {
            int n = i >> 4, j = i & 15;
            outp[i] = sx4[n * (SXS / 4) + j];
        }
    }
}

extern "C" void kernel_launch(void* const* d_in, const int* in_sizes, int n_in,
                              void* d_out, int out_size) {
    const float* G     = (const float*)d_in[0];
    const int* mk      = (const int*)d_in[1];
    const float* r     = (const float*)d_in[2];
    const float* in_w  = (const float*)d_in[3];
    const float* in_b  = (const float*)d_in[4];
    const float* out_w = (const float*)d_in[5];
    const float* out_b = (const float*)d_in[6];
    const float* ln_g  = (const float*)d_in[7];
    const float* ln_b  = (const float*)d_in[8];
    float* out         = (float*)d_out;

    int B = in_sizes[0] / (NNEI * ED);

    cudaFuncSetAttribute(nwa_kernel, cudaFuncAttributeMaxDynamicSharedMemorySize,
                         SMEM_FLOATS * sizeof(float));
    nwa_kernel<<<B, NTHREADS, SMEM_FLOATS * sizeof(float)>>>(
        G, mk, r, in_w, in_b, out_w, out_b, ln_g, ln_b, out);
}